// round 12
// baseline (speedup 1.0000x reference)
#include <cuda_runtime.h>
#include <cuda_bf16.h>
#include <cstdint>
#include <cstddef>

#define B_ 32
#define T_ 64
#define S_ 64
#define H_ 256
#define V_ 32000
#define NC 64          /* persistent scan CTAs */

// ---------------- device scratch (no runtime allocations allowed) ----------------
__device__ __align__(16) float g_annproj[B_ * S_ * H_];      // ann @ W1[H:] + b1
__device__ __align__(16) float g_xWi[B_ * T_ * 3 * H_];      // emb[tok] @ Wi*[H:] + bi*
__device__ __align__(16) float g_hidden[B_ * T_ * H_];       // scan outputs, tf32-rounded
__device__ __align__(16) float g_wout[(size_t)H_ * V_];      // Wout, tf32-rounded
__device__ __align__(16) float g_H[B_ * H_];                 // current hidden (fp32)
__device__ __align__(16) float g_Q[B_ * H_];                 // h @ W1[:H]
__device__ __align__(16) float g_CTX[B_ * H_];               // attention context
__device__ int g_bar[256];                                   // grid-barrier slots

__device__ __forceinline__ float f2tf_val(float x) {
    unsigned r;
    asm("cvt.rna.tf32.f32 %0, %1;" : "=r"(r) : "f"(x));
    return __uint_as_float(r);
}

__device__ __forceinline__ void fma4(float4& a, const float4 x, const float4 w) {
    a.x = fmaf(x.x, w.x, a.x); a.y = fmaf(x.y, w.y, a.y);
    a.z = fmaf(x.z, w.z, a.z); a.w = fmaf(x.w, w.w, a.w);
}

__device__ __forceinline__ void grid_barrier(int slot) {
    __syncthreads();
    if (threadIdx.x == 0) {
        __threadfence();
        atomicAdd(&g_bar[slot], 1);
        while (*((volatile int*)&g_bar[slot]) < NC) { }
        __threadfence();
    }
    __syncthreads();
}

// =========================================================================
// Kernel 1: precompute annproj and xWi; also zero the grid-barrier slots.
// grid.x = 512: kind = bid>>7 (0=ann,1=z,2=r,3=h), tile = bid&127.
// =========================================================================
__global__ __launch_bounds__(256) void prep_kernel(
    const int* __restrict__ inputs, const float* __restrict__ ann,
    const float* __restrict__ emb,
    const float* __restrict__ W1,  const float* __restrict__ b1,
    const float* __restrict__ Wiz, const float* __restrict__ biz,
    const float* __restrict__ Wir, const float* __restrict__ bir,
    const float* __restrict__ Wih, const float* __restrict__ bih)
{
    __shared__ float a_s[16][H_];
    __shared__ int s_tok[16];
    const int tid  = threadIdx.x;
    const int kind = blockIdx.x >> 7;
    const int r0   = (blockIdx.x & 127) * 16;

    if (blockIdx.x == 0) g_bar[tid] = 0;      // reset barriers each launch

    if (kind != 0 && tid < 16) s_tok[tid] = inputs[r0 + tid];
    __syncthreads();

    #pragma unroll
    for (int it = 0; it < 4; it++) {
        int id = tid + it * 256;
        int r  = id >> 6;
        int q  = id & 63;
        const float* src = (kind == 0)
            ? ann + (size_t)(r0 + r) * H_
            : emb + (size_t)s_tok[r] * H_;
        ((float4*)&a_s[r][0])[q] = ((const float4*)src)[q];
    }
    __syncthreads();

    const float* W; const float* bias;
    if (kind == 0)      { W = W1  + H_ * H_; bias = b1;  }
    else if (kind == 1) { W = Wiz + H_ * H_; bias = biz; }
    else if (kind == 2) { W = Wir + H_ * H_; bias = bir; }
    else                { W = Wih + H_ * H_; bias = bih; }

    const int j = tid;
    float acc[16];
    const float bj = bias[j];
    #pragma unroll
    for (int r = 0; r < 16; r++) acc[r] = bj;

    const float* Wj = W + j;
    #pragma unroll 2
    for (int k4 = 0; k4 < H_ / 4; k4++) {
        float w0 = Wj[(size_t)(4 * k4 + 0) * H_];
        float w1 = Wj[(size_t)(4 * k4 + 1) * H_];
        float w2 = Wj[(size_t)(4 * k4 + 2) * H_];
        float w3 = Wj[(size_t)(4 * k4 + 3) * H_];
        #pragma unroll
        for (int r = 0; r < 16; r++) {
            float4 a4 = *(const float4*)&a_s[r][k4 * 4];
            acc[r] = fmaf(a4.x, w0, acc[r]);
            acc[r] = fmaf(a4.y, w1, acc[r]);
            acc[r] = fmaf(a4.z, w2, acc[r]);
            acc[r] = fmaf(a4.w, w3, acc[r]);
        }
    }

    if (kind == 0) {
        #pragma unroll
        for (int r = 0; r < 16; r++)
            g_annproj[(size_t)(r0 + r) * H_ + j] = acc[r];
    } else {
        const int g = kind - 1;
        #pragma unroll
        for (int r = 0; r < 16; r++)
            g_xWi[((size_t)(r0 + r) * 3 + g) * H_ + j] = acc[r];
    }
}

// =========================================================================
// Kernel 1b: round Wout to tf32 once.
// =========================================================================
__global__ __launch_bounds__(256) void wout_cvt_kernel(const float* __restrict__ Wout)
{
    size_t idx = ((size_t)blockIdx.x * 256 + threadIdx.x) * 4;
    float4 v = *(const float4*)(Wout + idx);
    v.x = f2tf_val(v.x); v.y = f2tf_val(v.y);
    v.z = f2tf_val(v.z); v.w = f2tf_val(v.w);
    *(float4*)(g_wout + idx) = v;
}

// =========================================================================
// Kernel 2: persistent scan. NC=64 CTAs, 256 threads. CTA c owns columns
// [4c,4c+4) of all 7 weight matrices, SMEM-resident. CTAs 0..31 additionally
// run attention for batch b=c (ann/annproj SMEM-resident).
// SMEM float offsets:
// =========================================================================
#define PS_ANN  0        /* 16384: ann[b=c]        (CTAs < 32) */
#define PS_AP   16384    /* 16384: annproj[b=c]    (CTAs < 32) */
#define PS_HX   32768    /* 8320 : h or ctx, [32][260] padded  */
#define PS_W    41088    /* 7168 : 28 weight columns x 256 k   */
#define PS_Q    48256    /* 256  : q row for attention         */
#define PS_HW   48512    /* 384  : hw[3][32][4]                */
#define PS_CI   48896    /* 384  : ci[3][32][4]                */
#define PS_W2   49280    /* 256  */
#define PS_AW   49536    /* 64   */
#define PS_U    49600    /* 64   */
#define PS_RED  49664    /* 8    */
#define PS_BIAS 49672    /* 12   */
#define PS_TOT  49688
#define PSCAN_SMEM_BYTES (PS_TOT * 4)

__global__ void __launch_bounds__(256, 1) scan_kernel(
    const float* __restrict__ ann,  const float* __restrict__ hinit,
    const float* __restrict__ W1,   const float* __restrict__ W2v,
    const float* __restrict__ b2,
    const float* __restrict__ Wiz,  const float* __restrict__ Wir,
    const float* __restrict__ Wih,
    const float* __restrict__ Whz,  const float* __restrict__ bhz,
    const float* __restrict__ Whr,  const float* __restrict__ bhr,
    const float* __restrict__ Whh,  const float* __restrict__ bhh,
    float* __restrict__ attn_out)
{
    extern __shared__ float sm[];
    float* s_ann  = sm + PS_ANN;
    float* s_ap   = sm + PS_AP;
    float* s_hx   = sm + PS_HX;
    float* s_w    = sm + PS_W;
    float* s_q    = sm + PS_Q;
    float* s_hw   = sm + PS_HW;
    float* s_ci   = sm + PS_CI;
    float* s_w2   = sm + PS_W2;
    float* s_aw   = sm + PS_AW;
    float* s_u    = sm + PS_U;
    float* s_red  = sm + PS_RED;
    float* s_bias = sm + PS_BIAS;

    const int c   = blockIdx.x;
    const int tid = threadIdx.x;
    const int c4  = c * 4;
    const int wid = tid >> 5, lane = tid & 31;

    // ---- one-time init: weight column slices [W1a,Whz,Whr,Whh,Wiz,Wir,Wih] ----
    {
        const float* Wm[7] = {W1, Whz, Whr, Whh, Wiz, Wir, Wih};
        for (int idx = tid; idx < 7 * 256; idx += 256) {
            int m7 = idx >> 8, k = idx & 255;
            float4 v = *(const float4*)(Wm[m7] + (size_t)k * H_ + c4);
            s_w[(m7 * 4 + 0) * 256 + k] = v.x;
            s_w[(m7 * 4 + 1) * 256 + k] = v.y;
            s_w[(m7 * 4 + 2) * 256 + k] = v.z;
            s_w[(m7 * 4 + 3) * 256 + k] = v.w;
        }
        if (tid < 12) {
            int m = tid >> 2, jj = tid & 3;
            const float* bp = (m == 0 ? bhz : m == 1 ? bhr : bhh);
            s_bias[tid] = bp[c4 + jj];
        }
        s_w2[tid] = W2v[tid];
        if (c < 32) {
            const float4* sa = (const float4*)(ann + (size_t)c * S_ * H_);
            const float4* sp = (const float4*)(g_annproj + (size_t)c * S_ * H_);
            #pragma unroll
            for (int i = 0; i < 16; i++) {
                int idx = tid + i * 256;
                ((float4*)s_ann)[idx] = sa[idx];
                ((float4*)s_ap)[idx]  = sp[idx];
            }
        }
    }
    const float b2v = b2[0];

    // phase-A role: 8 warps = (matrix mA in {W1a,Whz,Whr,Whh}) x (col-pair jpA)
    const int mA  = wid >> 1;
    const int jpA = wid & 1;
    // gates role
    const int gb = tid & 31;
    const int gj = tid >> 5;    // valid when tid < 128

    __syncthreads();

    for (int t = 0; t < T_; t++) {
        // ---- load H (or hinit at t=0) into s_hx[32][260] ----
        {
            const float4* src = (const float4*)((t == 0) ? hinit : g_H);
            #pragma unroll
            for (int i = 0; i < 8; i++) {
                int idx = tid + i * 256;
                int b = idx >> 6, kq = idx & 63;
                *(float4*)&s_hx[b * 260 + 4 * kq] = src[idx];
            }
        }
        __syncthreads();

        // ================= phase A: q / hw columns for all batches =========
        {
            const float4* wc0 = (const float4*)(s_w + (mA * 4 + 2 * jpA) * 256);
            const float4* wc1 = wc0 + 64;
            const float4* hp  = (const float4*)(s_hx + lane * 260);
            float4 a0 = make_float4(0.f, 0.f, 0.f, 0.f);
            float4 a1 = make_float4(0.f, 0.f, 0.f, 0.f);
            #pragma unroll 8
            for (int k4 = 0; k4 < 64; k4++) {
                float4 h4 = hp[k4];
                fma4(a0, h4, wc0[k4]);
                fma4(a1, h4, wc1[k4]);
            }
            float s0 = (a0.x + a0.y) + (a0.z + a0.w);
            float s1 = (a1.x + a1.y) + (a1.z + a1.w);
            const int j0 = 2 * jpA;
            if (mA == 0) {
                g_Q[lane * H_ + c4 + j0]     = s0;
                g_Q[lane * H_ + c4 + j0 + 1] = s1;
            } else {
                const int mb = mA - 1;
                s_hw[(mb * 32 + lane) * 4 + j0]     = s0 + s_bias[mb * 4 + j0];
                s_hw[(mb * 32 + lane) * 4 + j0 + 1] = s1 + s_bias[mb * 4 + j0 + 1];
            }
        }
        grid_barrier(3 * t + 0);

        // ================= phase B: attention for batch b = c (CTAs < 32) ==
        if (c < 32) {
            s_q[tid] = g_Q[c * H_ + tid];
            __syncthreads();
            {   // scores
                const int si = tid >> 2, p = tid & 3;
                float part = 0.f;
                #pragma unroll
                for (int i = 0; i < 64; i++) {
                    int jj = p + 4 * ((i + si) & 63);
                    float v = fmaxf(s_q[jj] + s_ap[si * H_ + jj], 0.f);
                    part = fmaf(v, s_w2[jj], part);
                }
                part += __shfl_xor_sync(0xffffffffu, part, 1);
                part += __shfl_xor_sync(0xffffffffu, part, 2);
                if (p == 0) s_u[si] = part + b2v;
            }
            __syncthreads();
            {   // softmax over 64 positions
                float uv = (tid < 64) ? s_u[tid] : -1e30f;
                if (tid < 64) {
                    float m = uv;
                    #pragma unroll
                    for (int o = 16; o > 0; o >>= 1)
                        m = fmaxf(m, __shfl_xor_sync(0xffffffffu, m, o));
                    if ((tid & 31) == 0) s_red[tid >> 5] = m;
                }
                __syncthreads();
                float gmax = fmaxf(s_red[0], s_red[1]);
                float ev = 0.f;
                if (tid < 64) {
                    ev = __expf(uv - gmax);
                    float ssum = ev;
                    #pragma unroll
                    for (int o = 16; o > 0; o >>= 1)
                        ssum += __shfl_xor_sync(0xffffffffu, ssum, o);
                    if ((tid & 31) == 0) s_red[2 + (tid >> 5)] = ssum;
                }
                __syncthreads();
                if (tid < 64) {
                    float aw = ev / (s_red[2] + s_red[3]);
                    s_aw[tid] = aw;
                    attn_out[(size_t)c * S_ * T_ + (size_t)tid * T_ + t] = aw;
                }
            }
            __syncthreads();
            {   // context
                float ctx = 0.f;
                #pragma unroll
                for (int s2 = 0; s2 < 64; s2++)
                    ctx = fmaf(s_aw[s2], s_ann[s2 * H_ + tid], ctx);
                g_CTX[c * H_ + tid] = ctx;
            }
        }

        // prefetch gate inputs (x-projections + owned h_prev) before barrier
        float xz = 0.f, xr = 0.f, xh = 0.f, hpv = 0.f;
        if (tid < 128) {
            const size_t xo = ((size_t)(gb * T_ + t) * 3) * H_ + c4 + gj;
            xz = g_xWi[xo]; xr = g_xWi[xo + H_]; xh = g_xWi[xo + 2 * H_];
            hpv = s_hx[gb * 260 + c4 + gj];
        }
        grid_barrier(3 * t + 1);

        // ================= phase C: ci columns + fused gates ===============
        {
            const float4* src = (const float4*)g_CTX;
            #pragma unroll
            for (int i = 0; i < 8; i++) {
                int idx = tid + i * 256;
                int b = idx >> 6, kq = idx & 63;
                *(float4*)&s_hx[b * 260 + 4 * kq] = src[idx];
            }
        }
        __syncthreads();
        if (wid < 6) {
            const int mC = wid >> 1, jpC = wid & 1;
            const float4* wc0 = (const float4*)(s_w + ((4 + mC) * 4 + 2 * jpC) * 256);
            const float4* wc1 = wc0 + 64;
            const float4* cp  = (const float4*)(s_hx + lane * 260);
            float4 a0 = make_float4(0.f, 0.f, 0.f, 0.f);
            float4 a1 = make_float4(0.f, 0.f, 0.f, 0.f);
            #pragma unroll 8
            for (int k4 = 0; k4 < 64; k4++) {
                float4 c4v = cp[k4];
                fma4(a0, c4v, wc0[k4]);
                fma4(a1, c4v, wc1[k4]);
            }
            const int j0 = 2 * jpC;
            s_ci[(mC * 32 + lane) * 4 + j0]     = (a0.x + a0.y) + (a0.z + a0.w);
            s_ci[(mC * 32 + lane) * 4 + j0 + 1] = (a1.x + a1.y) + (a1.z + a1.w);
        }
        __syncthreads();
        if (tid < 128) {
            float hwz = s_hw[(0 * 32 + gb) * 4 + gj];
            float hwr = s_hw[(1 * 32 + gb) * 4 + gj];
            float hwh = s_hw[(2 * 32 + gb) * 4 + gj];
            float ciz = s_ci[(0 * 32 + gb) * 4 + gj];
            float cir = s_ci[(1 * 32 + gb) * 4 + gj];
            float cih = s_ci[(2 * 32 + gb) * 4 + gj];
            float z = 1.f / (1.f + __expf(-(ciz + xz + hwz)));
            float r = 1.f / (1.f + __expf(-(cir + xr + hwr)));
            float g = tanhf(cih + xh + r * hwh);
            float hn = (1.f - z) * g + z * hpv;
            g_H[gb * H_ + c4 + gj] = hn;
            g_hidden[(size_t)(gb * T_ + t) * H_ + c4 + gj] = f2tf_val(hn);
        }
        grid_barrier(3 * t + 2);
    }
}

// =========================================================================
// Kernel 3: out[B*T, V] = hiddens @ Wout + bout (pre-rounded tf32 operands)
// tf32 mma m16n8k8, CTA tile 128x64, cp.async double-buffered.
// =========================================================================
#define GBM 128
#define GBN 64
#define GBK 32
#define AS_STRIDE 36
#define BS_STRIDE 72
#define GEMM_SMEM_FLOATS (2 * GBM * AS_STRIDE + 2 * GBK * BS_STRIDE)
#define GEMM_SMEM_BYTES  (GEMM_SMEM_FLOATS * 4)

__device__ __forceinline__ void cpasync16(void* smem_dst, const void* gsrc) {
    unsigned s = (unsigned)__cvta_generic_to_shared(smem_dst);
    asm volatile("cp.async.ca.shared.global [%0], [%1], 16;" :: "r"(s), "l"(gsrc));
}

__global__ __launch_bounds__(256) void out_gemm_kernel(
    const float* __restrict__ bout, float* __restrict__ out)
{
    extern __shared__ float gsm[];
    float* As = gsm;
    float* Bs = gsm + 2 * GBM * AS_STRIDE;

    const int tid  = threadIdx.x;
    const int wid  = tid >> 5;
    const int lane = tid & 31;
    const int g    = lane >> 2;
    const int tq   = lane & 3;
    const int wm   = wid & 3;
    const int wn   = wid >> 2;
    const int m0   = blockIdx.x * GBM;
    const int n0   = blockIdx.y * GBN;

    float c[2][4][4];
    #pragma unroll
    for (int a = 0; a < 2; a++)
        #pragma unroll
        for (int bb = 0; bb < 4; bb++)
            #pragma unroll
            for (int cc = 0; cc < 4; cc++) c[a][bb][cc] = 0.f;

    auto issue = [&](int kc_i) {
        const int kc = kc_i * GBK;
        float* Ab = As + (kc_i & 1) * GBM * AS_STRIDE;
        float* Bb = Bs + (kc_i & 1) * GBK * BS_STRIDE;
        #pragma unroll
        for (int it = 0; it < 4; it++) {
            int id = tid + it * 256;
            int m  = id >> 3;
            int q  = id & 7;
            cpasync16(&Ab[m * AS_STRIDE + q * 4],
                      &g_hidden[(size_t)(m0 + m) * H_ + kc + q * 4]);
        }
        #pragma unroll
        for (int it = 0; it < 2; it++) {
            int id = tid + it * 256;
            int k  = id >> 4;
            int nq = id & 15;
            cpasync16(&Bb[k * BS_STRIDE + nq * 4],
                      &g_wout[(size_t)(kc + k) * V_ + n0 + nq * 4]);
        }
        asm volatile("cp.async.commit_group;");
    };

    issue(0);

    for (int kc_i = 0; kc_i < H_ / GBK; kc_i++) {
        if (kc_i + 1 < H_ / GBK) {
            issue(kc_i + 1);
            asm volatile("cp.async.wait_group 1;");
        } else {
            asm volatile("cp.async.wait_group 0;");
        }
        __syncthreads();

        const float* Ab = As + (kc_i & 1) * GBM * AS_STRIDE;
        const float* Bb = Bs + (kc_i & 1) * GBK * BS_STRIDE;

        #pragma unroll
        for (int ks = 0; ks < 4; ks++) {
            const int K0 = ks * 8;
            unsigned af[2][4];
            #pragma unroll
            for (int mt = 0; mt < 2; mt++) {
                int row = wm * 32 + mt * 16 + g;
                af[mt][0] = __float_as_uint(Ab[(row    ) * AS_STRIDE + K0 + tq    ]);
                af[mt][1] = __float_as_uint(Ab[(row + 8) * AS_STRIDE + K0 + tq    ]);
                af[mt][2] = __float_as_uint(Ab[(row    ) * AS_STRIDE + K0 + tq + 4]);
                af[mt][3] = __float_as_uint(Ab[(row + 8) * AS_STRIDE + K0 + tq + 4]);
            }
            unsigned bf[4][2];
            #pragma unroll
            for (int nt = 0; nt < 4; nt++) {
                int col = wn * 32 + nt * 8 + g;
                bf[nt][0] = __float_as_uint(Bb[(K0 + tq    ) * BS_STRIDE + col]);
                bf[nt][1] = __float_as_uint(Bb[(K0 + tq + 4) * BS_STRIDE + col]);
            }
            #pragma unroll
            for (int mt = 0; mt < 2; mt++)
                #pragma unroll
                for (int nt = 0; nt < 4; nt++) {
                    asm volatile(
                        "mma.sync.aligned.m16n8k8.row.col.f32.tf32.tf32.f32 "
                        "{%0,%1,%2,%3}, {%4,%5,%6,%7}, {%8,%9}, {%0,%1,%2,%3};"
                        : "+f"(c[mt][nt][0]), "+f"(c[mt][nt][1]),
                          "+f"(c[mt][nt][2]), "+f"(c[mt][nt][3])
                        : "r"(af[mt][0]), "r"(af[mt][1]),
                          "r"(af[mt][2]), "r"(af[mt][3]),
                          "r"(bf[nt][0]), "r"(bf[nt][1]));
                }
        }
        __syncthreads();
    }

    #pragma unroll
    for (int mt = 0; mt < 2; mt++) {
        #pragma unroll
        for (int nt = 0; nt < 4; nt++) {
            int row = m0 + wm * 32 + mt * 16 + g;
            int col = n0 + wn * 32 + nt * 8 + 2 * tq;
            float bo0 = bout[col], bo1 = bout[col + 1];
            float2 v0 = make_float2(c[mt][nt][0] + bo0, c[mt][nt][1] + bo1);
            float2 v1 = make_float2(c[mt][nt][2] + bo0, c[mt][nt][3] + bo1);
            *(float2*)&out[(size_t)row * V_ + col]       = v0;
            *(float2*)&out[(size_t)(row + 8) * V_ + col] = v1;
        }
    }
}

// =========================================================================
extern "C" void kernel_launch(void* const* d_in, const int* in_sizes, int n_in,
                              void* d_out, int out_size)
{
    const int*   inputs = (const int*)  d_in[0];
    const float* ann    = (const float*)d_in[1];
    const float* hinit  = (const float*)d_in[2];
    const float* emb    = (const float*)d_in[3];
    const float* W1     = (const float*)d_in[4];
    const float* b1     = (const float*)d_in[5];
    const float* W2v    = (const float*)d_in[6];
    const float* b2     = (const float*)d_in[7];
    const float* Wiz    = (const float*)d_in[8];
    const float* biz    = (const float*)d_in[9];
    const float* Wir    = (const float*)d_in[10];
    const float* bir    = (const float*)d_in[11];
    const float* Wih    = (const float*)d_in[12];
    const float* bih    = (const float*)d_in[13];
    const float* Whz    = (const float*)d_in[14];
    const float* bhz    = (const float*)d_in[15];
    const float* Whr    = (const float*)d_in[16];
    const float* bhr    = (const float*)d_in[17];
    const float* Whh    = (const float*)d_in[18];
    const float* bhh    = (const float*)d_in[19];
    const float* Wout   = (const float*)d_in[20];
    const float* bout   = (const float*)d_in[21];

    float* out  = (float*)d_out;
    float* attn = out + (size_t)B_ * T_ * V_;   // outputs: (B,T,V) then (B,S,T)

    cudaFuncSetAttribute(scan_kernel,
                         cudaFuncAttributeMaxDynamicSharedMemorySize,
                         PSCAN_SMEM_BYTES);
    cudaFuncSetAttribute(out_gemm_kernel,
                         cudaFuncAttributeMaxDynamicSharedMemorySize,
                         GEMM_SMEM_BYTES);

    prep_kernel<<<512, 256>>>(inputs, ann, emb, W1, b1,
                              Wiz, biz, Wir, bir, Wih, bih);
    wout_cvt_kernel<<<8000, 256>>>(Wout);
    scan_kernel<<<NC, 256, PSCAN_SMEM_BYTES>>>(ann, hinit, W1, W2v, b2,
                                               Wiz, Wir, Wih,
                                               Whz, bhz, Whr, bhr, Whh, bhh,
                                               attn);
    out_gemm_kernel<<<dim3(16, 500), 256, GEMM_SMEM_BYTES>>>(bout, out);
}

// round 13
// speedup vs baseline: 1.7201x; 1.7201x over previous
#include <cuda_runtime.h>
#include <cuda_bf16.h>
#include <cstdint>
#include <cstddef>

#define B_ 32
#define T_ 64
#define S_ 64
#define H_ 256
#define V_ 32000

// ---------------- device scratch (no runtime allocations allowed) ----------------
__device__ __align__(16) float g_annproj[B_ * S_ * H_];      // ann @ W1[H:] + b1
__device__ __align__(16) float g_xWi[B_ * T_ * 3 * H_];      // emb[tok] @ Wi*[H:] + bi*
__device__ __align__(16) float g_hidden[B_ * T_ * H_];       // scan outputs, tf32-rounded
__device__ __align__(16) float g_wout[(size_t)H_ * V_];      // Wout, tf32-rounded

__device__ __forceinline__ float f2tf_val(float x) {
    unsigned r;
    asm("cvt.rna.tf32.f32 %0, %1;" : "=r"(r) : "f"(x));
    return __uint_as_float(r);
}

// =========================================================================
// Kernel 1: precompute annproj and xWi.  16 output rows per block.
// grid.x = 512: kind = bid>>7 (0=ann,1=z,2=r,3=h), tile = bid&127.
// =========================================================================
__global__ __launch_bounds__(256) void prep_kernel(
    const int* __restrict__ inputs, const float* __restrict__ ann,
    const float* __restrict__ emb,
    const float* __restrict__ W1,  const float* __restrict__ b1,
    const float* __restrict__ Wiz, const float* __restrict__ biz,
    const float* __restrict__ Wir, const float* __restrict__ bir,
    const float* __restrict__ Wih, const float* __restrict__ bih)
{
    __shared__ float a_s[16][H_];
    __shared__ int s_tok[16];
    const int tid  = threadIdx.x;
    const int kind = blockIdx.x >> 7;
    const int r0   = (blockIdx.x & 127) * 16;

    if (kind != 0 && tid < 16) s_tok[tid] = inputs[r0 + tid];
    __syncthreads();

    #pragma unroll
    for (int it = 0; it < 4; it++) {
        int id = tid + it * 256;
        int r  = id >> 6;
        int q  = id & 63;
        const float* src = (kind == 0)
            ? ann + (size_t)(r0 + r) * H_
            : emb + (size_t)s_tok[r] * H_;
        ((float4*)&a_s[r][0])[q] = ((const float4*)src)[q];
    }
    __syncthreads();

    const float* W; const float* bias;
    if (kind == 0)      { W = W1  + H_ * H_; bias = b1;  }
    else if (kind == 1) { W = Wiz + H_ * H_; bias = biz; }
    else if (kind == 2) { W = Wir + H_ * H_; bias = bir; }
    else                { W = Wih + H_ * H_; bias = bih; }

    const int j = tid;
    float acc[16];
    const float bj = bias[j];
    #pragma unroll
    for (int r = 0; r < 16; r++) acc[r] = bj;

    const float* Wj = W + j;
    #pragma unroll 2
    for (int k4 = 0; k4 < H_ / 4; k4++) {
        float w0 = Wj[(size_t)(4 * k4 + 0) * H_];
        float w1 = Wj[(size_t)(4 * k4 + 1) * H_];
        float w2 = Wj[(size_t)(4 * k4 + 2) * H_];
        float w3 = Wj[(size_t)(4 * k4 + 3) * H_];
        #pragma unroll
        for (int r = 0; r < 16; r++) {
            float4 a4 = *(const float4*)&a_s[r][k4 * 4];
            acc[r] = fmaf(a4.x, w0, acc[r]);
            acc[r] = fmaf(a4.y, w1, acc[r]);
            acc[r] = fmaf(a4.z, w2, acc[r]);
            acc[r] = fmaf(a4.w, w3, acc[r]);
        }
    }

    if (kind == 0) {
        #pragma unroll
        for (int r = 0; r < 16; r++)
            g_annproj[(size_t)(r0 + r) * H_ + j] = acc[r];
    } else {
        const int g = kind - 1;
        #pragma unroll
        for (int r = 0; r < 16; r++)
            g_xWi[((size_t)(r0 + r) * 3 + g) * H_ + j] = acc[r];
    }
}

// =========================================================================
// Kernel 1b: round Wout to tf32 once.
// =========================================================================
__global__ __launch_bounds__(256) void wout_cvt_kernel(const float* __restrict__ Wout)
{
    size_t idx = ((size_t)blockIdx.x * 256 + threadIdx.x) * 4;
    float4 v = *(const float4*)(Wout + idx);
    v.x = f2tf_val(v.x); v.y = f2tf_val(v.y);
    v.z = f2tf_val(v.z); v.w = f2tf_val(v.w);
    *(float4*)(g_wout + idx) = v;
}

// =========================================================================
// Kernel 2: cluster-pair scan. Grid 64, cluster(2,1,1): cluster = one batch,
// rank r owns output columns [128r, 128r+128) of all 7 weight matrices.
// 512 threads/CTA. Cross-CTA state via st.shared::cluster + barrier.cluster.
// SMEM float offsets (per CTA):
// =========================================================================
#define X_ANN  0        /* 8192: ann[b][s][own 128 j]    */
#define X_AP   8192     /* 8192: annproj half            */
#define X_H    16384    /* 256 : full h (peer fills other half) */
#define X_Q    16640    /* 128 : q own columns           */
#define X_HW   16768    /* 384 : hw[3][128]              */
#define X_CI   17152    /* 384 : ci[3][128]              */
#define X_CTX  17536    /* 256 : full ctx                */
#define X_W2   17792    /* 128 : W2 own columns          */
#define X_U    17920    /* 64  : own score partials      */
#define X_UP   17984    /* 64  : peer score partials     */
#define X_AW   18048    /* 64  */
#define X_RED  18112    /* 8   */
#define X_BIAS 18120    /* 384 : bh[3][128] own columns  */
#define X_P1   18504    /* 512 : stage-1 kh=1 partials   */
#define X_P5   19016    /* 384 : stage-5 kh=1 partials   */
#define X_TOT  19400
#define CSCAN_SMEM_BYTES (X_TOT * 4)

__device__ __forceinline__ void st_peer(uint32_t pbase, int foff, float v) {
    asm volatile("st.shared::cluster.f32 [%0], %1;"
                 :: "r"(pbase + 4u * (uint32_t)foff), "f"(v) : "memory");
}

__device__ __forceinline__ void cluster_sync_all() {
    __syncthreads();
    asm volatile("barrier.cluster.arrive.aligned;" ::: "memory");
    asm volatile("barrier.cluster.wait.aligned;" ::: "memory");
}

__global__ void __cluster_dims__(2, 1, 1) __launch_bounds__(512, 1) scan_kernel(
    const float* __restrict__ ann,  const float* __restrict__ hinit,
    const float* __restrict__ W1,   const float* __restrict__ W2v,
    const float* __restrict__ b2,
    const float* __restrict__ Wiz,  const float* __restrict__ Wir,
    const float* __restrict__ Wih,
    const float* __restrict__ Whz,  const float* __restrict__ bhz,
    const float* __restrict__ Whr,  const float* __restrict__ bhr,
    const float* __restrict__ Whh,  const float* __restrict__ bhh,
    float* __restrict__ attn_out)
{
    extern __shared__ float sm[];

    const int cid  = blockIdx.x;
    const int b    = cid >> 1;
    const int rank = cid & 1;
    const int j0   = rank * 128;
    const int tid  = threadIdx.x;

    uint32_t sbase = (uint32_t)__cvta_generic_to_shared(sm);
    uint32_t pbase;
    asm("mapa.shared::cluster.u32 %0, %1, %2;"
        : "=r"(pbase) : "r"(sbase), "r"(rank ^ 1));

    // ---- one-time init ----
    #pragma unroll
    for (int i = 0; i < 4; i++) {
        int idx = tid + i * 512;            // 0..2047 float4 slots
        int row = idx >> 5, q = idx & 31;   // 32 float4 per 128-float row
        ((float4*)(sm + X_ANN))[idx] =
            *(const float4*)(ann + (size_t)b * S_ * H_ + (size_t)row * H_ + j0 + 4 * q);
        ((float4*)(sm + X_AP))[idx] =
            *(const float4*)(g_annproj + (size_t)b * S_ * H_ + (size_t)row * H_ + j0 + 4 * q);
    }
    if (tid < 256) sm[X_H + tid] = hinit[(size_t)b * H_ + tid];
    if (tid < 128) sm[X_W2 + tid] = W2v[j0 + tid];
    if (tid < 384) {
        int m = tid >> 7, jj = tid & 127;
        const float* bp = (m == 0 ? bhz : m == 1 ? bhr : bhh);
        sm[X_BIAS + tid] = bp[j0 + jj];
    }
    const float b2v = b2[0];

    // ---- per-thread roles ----
    const int m1 = tid >> 7;            // 0..3 (stage1); 0..2 valid for stage5
    const int kh = (tid >> 6) & 1;      // k-half
    const int cp = tid & 63;            // column pair (2 cols)
    const float* Ws1 = (m1 == 0 ? W1 : m1 == 1 ? Whz : m1 == 2 ? Whr : Whh);
    const float* Ws5 = (m1 == 0 ? Wiz : m1 == 1 ? Wir : Wih);
    const float2* wb1 = (const float2*)(Ws1 + (size_t)kh * 128 * H_ + j0 + 2 * cp);
    const float2* wb5 = (const float2*)(Ws5 + (size_t)kh * 128 * H_ + j0 + 2 * cp);

    cluster_sync_all();

    for (int t = 0; t < T_; t++) {
        // ========== stage 1: q / hw columns (k-split by 2) ==========
        {
            float ax0 = 0.f, ay0 = 0.f, ax1 = 0.f, ay1 = 0.f;
            const float4* hp = (const float4*)(sm + X_H) + kh * 32;
            #pragma unroll 4
            for (int k4 = 0; k4 < 32; k4++) {
                float4 h4 = hp[k4];
                float2 w0 = wb1[(4 * k4 + 0) * 128];
                float2 w1 = wb1[(4 * k4 + 1) * 128];
                float2 w2 = wb1[(4 * k4 + 2) * 128];
                float2 w3 = wb1[(4 * k4 + 3) * 128];
                ax0 = fmaf(h4.x, w0.x, ax0); ay0 = fmaf(h4.x, w0.y, ay0);
                ax1 = fmaf(h4.y, w1.x, ax1); ay1 = fmaf(h4.y, w1.y, ay1);
                ax0 = fmaf(h4.z, w2.x, ax0); ay0 = fmaf(h4.z, w2.y, ay0);
                ax1 = fmaf(h4.w, w3.x, ax1); ay1 = fmaf(h4.w, w3.y, ay1);
            }
            float sx = ax0 + ax1, sy = ay0 + ay1;
            if (kh == 1) {
                sm[X_P1 + (m1 * 64 + cp) * 2]     = sx;
                sm[X_P1 + (m1 * 64 + cp) * 2 + 1] = sy;
            }
            __syncthreads();
            if (kh == 0) {
                float ox = sx + sm[X_P1 + (m1 * 64 + cp) * 2];
                float oy = sy + sm[X_P1 + (m1 * 64 + cp) * 2 + 1];
                if (m1 == 0) {
                    sm[X_Q + 2 * cp]     = ox;
                    sm[X_Q + 2 * cp + 1] = oy;
                } else {
                    ox += sm[X_BIAS + (m1 - 1) * 128 + 2 * cp];
                    oy += sm[X_BIAS + (m1 - 1) * 128 + 2 * cp + 1];
                    sm[X_HW + (m1 - 1) * 128 + 2 * cp]     = ox;
                    sm[X_HW + (m1 - 1) * 128 + 2 * cp + 1] = oy;
                }
            }
        }
        __syncthreads();

        // ========== stage 2: partial scores over own 128 columns ==========
        {
            const int s = tid >> 3, p = tid & 7;
            float part = 0.f;
            #pragma unroll
            for (int i = 0; i < 16; i++) {
                int jj = p + 8 * ((i + s) & 15);    // conflict-free rotation
                float v = fmaxf(sm[X_Q + jj] + sm[X_AP + s * 128 + jj], 0.f);
                part = fmaf(v, sm[X_W2 + jj], part);
            }
            part += __shfl_xor_sync(0xffffffffu, part, 1);
            part += __shfl_xor_sync(0xffffffffu, part, 2);
            part += __shfl_xor_sync(0xffffffffu, part, 4);
            if (p == 0) {
                sm[X_U + s] = part;
                st_peer(pbase, X_UP + s, part);
            }
        }
        cluster_sync_all();   // #1: score partials exchanged

        // ========== stage 3: softmax (computed on both ranks) ==========
        {
            float uv = -1e30f;
            if (tid < 64) uv = sm[X_U + tid] + sm[X_UP + tid] + b2v;
            if (tid < 64) {
                float m = uv;
                #pragma unroll
                for (int o = 16; o > 0; o >>= 1)
                    m = fmaxf(m, __shfl_xor_sync(0xffffffffu, m, o));
                if ((tid & 31) == 0) sm[X_RED + (tid >> 5)] = m;
            }
            __syncthreads();
            float gmax = fmaxf(sm[X_RED], sm[X_RED + 1]);
            float ev = 0.f;
            if (tid < 64) {
                ev = __expf(uv - gmax);
                float ssum = ev;
                #pragma unroll
                for (int o = 16; o > 0; o >>= 1)
                    ssum += __shfl_xor_sync(0xffffffffu, ssum, o);
                if ((tid & 31) == 0) sm[X_RED + 2 + (tid >> 5)] = ssum;
            }
            __syncthreads();
            if (tid < 64) {
                float aw = ev / (sm[X_RED + 2] + sm[X_RED + 3]);
                sm[X_AW + tid] = aw;
                if (rank == 0)
                    attn_out[(size_t)b * S_ * T_ + (size_t)tid * T_ + t] = aw;
            }
        }
        __syncthreads();

        // ========== stage 4: context over own columns + xWi prefetch ======
        float xz = 0.f, xr = 0.f, xh = 0.f;
        if (tid < 128) {
            const size_t xo = ((size_t)(b * T_ + t) * 3) * H_ + j0 + tid;
            xz = g_xWi[xo]; xr = g_xWi[xo + H_]; xh = g_xWi[xo + 2 * H_];
            float ctx = 0.f;
            #pragma unroll
            for (int s2 = 0; s2 < 64; s2++)
                ctx = fmaf(sm[X_AW + s2], sm[X_ANN + s2 * 128 + tid], ctx);
            sm[X_CTX + j0 + tid] = ctx;
            st_peer(pbase, X_CTX + j0 + tid, ctx);
        }
        cluster_sync_all();   // #2: full ctx assembled on both ranks

        // ========== stage 5: ci = ctx @ Wi*[:H] own columns ==========
        {
            float ax0 = 0.f, ay0 = 0.f, ax1 = 0.f, ay1 = 0.f;
            if (m1 < 3) {
                const float4* cpv = (const float4*)(sm + X_CTX) + kh * 32;
                #pragma unroll 4
                for (int k4 = 0; k4 < 32; k4++) {
                    float4 c4 = cpv[k4];
                    float2 w0 = wb5[(4 * k4 + 0) * 128];
                    float2 w1 = wb5[(4 * k4 + 1) * 128];
                    float2 w2 = wb5[(4 * k4 + 2) * 128];
                    float2 w3 = wb5[(4 * k4 + 3) * 128];
                    ax0 = fmaf(c4.x, w0.x, ax0); ay0 = fmaf(c4.x, w0.y, ay0);
                    ax1 = fmaf(c4.y, w1.x, ax1); ay1 = fmaf(c4.y, w1.y, ay1);
                    ax0 = fmaf(c4.z, w2.x, ax0); ay0 = fmaf(c4.z, w2.y, ay0);
                    ax1 = fmaf(c4.w, w3.x, ax1); ay1 = fmaf(c4.w, w3.y, ay1);
                }
            }
            float sx = ax0 + ax1, sy = ay0 + ay1;
            if (m1 < 3 && kh == 1) {
                sm[X_P5 + (m1 * 64 + cp) * 2]     = sx;
                sm[X_P5 + (m1 * 64 + cp) * 2 + 1] = sy;
            }
            __syncthreads();
            if (m1 < 3 && kh == 0) {
                sm[X_CI + m1 * 128 + 2 * cp] =
                    sx + sm[X_P5 + (m1 * 64 + cp) * 2];
                sm[X_CI + m1 * 128 + 2 * cp + 1] =
                    sy + sm[X_P5 + (m1 * 64 + cp) * 2 + 1];
            }
        }
        __syncthreads();

        // ========== stage 6: GRU gates for own columns ==========
        if (tid < 128) {
            const int j = tid;
            float hprev = sm[X_H + j0 + j];
            float z = 1.f / (1.f + __expf(-(sm[X_CI + j]       + xz + sm[X_HW + j])));
            float r = 1.f / (1.f + __expf(-(sm[X_CI + 128 + j] + xr + sm[X_HW + 128 + j])));
            float g = tanhf(sm[X_CI + 256 + j] + xh + r * sm[X_HW + 256 + j]);
            float hn = (1.f - z) * g + z * hprev;
            sm[X_H + j0 + j] = hn;
            st_peer(pbase, X_H + j0 + j, hn);
            g_hidden[(size_t)(b * T_ + t) * H_ + j0 + j] = f2tf_val(hn);
        }
        cluster_sync_all();   // #3: full h_new on both ranks
    }
}

// =========================================================================
// Kernel 3: out[B*T, V] = hiddens @ Wout + bout (pre-rounded tf32 operands)
// tf32 mma m16n8k8, CTA tile 128x64, cp.async double-buffered.
// =========================================================================
#define GBM 128
#define GBN 64
#define GBK 32
#define AS_STRIDE 36
#define BS_STRIDE 72
#define GEMM_SMEM_FLOATS (2 * GBM * AS_STRIDE + 2 * GBK * BS_STRIDE)
#define GEMM_SMEM_BYTES  (GEMM_SMEM_FLOATS * 4)

__device__ __forceinline__ void cpasync16(void* smem_dst, const void* gsrc) {
    unsigned s = (unsigned)__cvta_generic_to_shared(smem_dst);
    asm volatile("cp.async.ca.shared.global [%0], [%1], 16;" :: "r"(s), "l"(gsrc));
}

__global__ __launch_bounds__(256) void out_gemm_kernel(
    const float* __restrict__ bout, float* __restrict__ out)
{
    extern __shared__ float gsm[];
    float* As = gsm;
    float* Bs = gsm + 2 * GBM * AS_STRIDE;

    const int tid  = threadIdx.x;
    const int wid  = tid >> 5;
    const int lane = tid & 31;
    const int g    = lane >> 2;
    const int tq   = lane & 3;
    const int wm   = wid & 3;
    const int wn   = wid >> 2;
    const int m0   = blockIdx.x * GBM;
    const int n0   = blockIdx.y * GBN;

    float c[2][4][4];
    #pragma unroll
    for (int a = 0; a < 2; a++)
        #pragma unroll
        for (int bb = 0; bb < 4; bb++)
            #pragma unroll
            for (int cc = 0; cc < 4; cc++) c[a][bb][cc] = 0.f;

    auto issue = [&](int kc_i) {
        const int kc = kc_i * GBK;
        float* Ab = As + (kc_i & 1) * GBM * AS_STRIDE;
        float* Bb = Bs + (kc_i & 1) * GBK * BS_STRIDE;
        #pragma unroll
        for (int it = 0; it < 4; it++) {
            int id = tid + it * 256;
            int m  = id >> 3;
            int q  = id & 7;
            cpasync16(&Ab[m * AS_STRIDE + q * 4],
                      &g_hidden[(size_t)(m0 + m) * H_ + kc + q * 4]);
        }
        #pragma unroll
        for (int it = 0; it < 2; it++) {
            int id = tid + it * 256;
            int k  = id >> 4;
            int nq = id & 15;
            cpasync16(&Bb[k * BS_STRIDE + nq * 4],
                      &g_wout[(size_t)(kc + k) * V_ + n0 + nq * 4]);
        }
        asm volatile("cp.async.commit_group;");
    };

    issue(0);

    for (int kc_i = 0; kc_i < H_ / GBK; kc_i++) {
        if (kc_i + 1 < H_ / GBK) {
            issue(kc_i + 1);
            asm volatile("cp.async.wait_group 1;");
        } else {
            asm volatile("cp.async.wait_group 0;");
        }
        __syncthreads();

        const float* Ab = As + (kc_i & 1) * GBM * AS_STRIDE;
        const float* Bb = Bs + (kc_i & 1) * GBK * BS_STRIDE;

        #pragma unroll
        for (int ks = 0; ks < 4; ks++) {
            const int K0 = ks * 8;
            unsigned af[2][4];
            #pragma unroll
            for (int mt = 0; mt < 2; mt++) {
                int row = wm * 32 + mt * 16 + g;
                af[mt][0] = __float_as_uint(Ab[(row    ) * AS_STRIDE + K0 + tq    ]);
                af[mt][1] = __float_as_uint(Ab[(row + 8) * AS_STRIDE + K0 + tq    ]);
                af[mt][2] = __float_as_uint(Ab[(row    ) * AS_STRIDE + K0 + tq + 4]);
                af[mt][3] = __float_as_uint(Ab[(row + 8) * AS_STRIDE + K0 + tq + 4]);
            }
            unsigned bf[4][2];
            #pragma unroll
            for (int nt = 0; nt < 4; nt++) {
                int col = wn * 32 + nt * 8 + g;
                bf[nt][0] = __float_as_uint(Bb[(K0 + tq    ) * BS_STRIDE + col]);
                bf[nt][1] = __float_as_uint(Bb[(K0 + tq + 4) * BS_STRIDE + col]);
            }
            #pragma unroll
            for (int mt = 0; mt < 2; mt++)
                #pragma unroll
                for (int nt = 0; nt < 4; nt++) {
                    asm volatile(
                        "mma.sync.aligned.m16n8k8.row.col.f32.tf32.tf32.f32 "
                        "{%0,%1,%2,%3}, {%4,%5,%6,%7}, {%8,%9}, {%0,%1,%2,%3};"
                        : "+f"(c[mt][nt][0]), "+f"(c[mt][nt][1]),
                          "+f"(c[mt][nt][2]), "+f"(c[mt][nt][3])
                        : "r"(af[mt][0]), "r"(af[mt][1]),
                          "r"(af[mt][2]), "r"(af[mt][3]),
                          "r"(bf[nt][0]), "r"(bf[nt][1]));
                }
        }
        __syncthreads();
    }

    #pragma unroll
    for (int mt = 0; mt < 2; mt++) {
        #pragma unroll
        for (int nt = 0; nt < 4; nt++) {
            int row = m0 + wm * 32 + mt * 16 + g;
            int col = n0 + wn * 32 + nt * 8 + 2 * tq;
            float bo0 = bout[col], bo1 = bout[col + 1];
            float2 v0 = make_float2(c[mt][nt][0] + bo0, c[mt][nt][1] + bo1);
            float2 v1 = make_float2(c[mt][nt][2] + bo0, c[mt][nt][3] + bo1);
            *(float2*)&out[(size_t)row * V_ + col]       = v0;
            *(float2*)&out[(size_t)(row + 8) * V_ + col] = v1;
        }
    }
}

// =========================================================================
extern "C" void kernel_launch(void* const* d_in, const int* in_sizes, int n_in,
                              void* d_out, int out_size)
{
    const int*   inputs = (const int*)  d_in[0];
    const float* ann    = (const float*)d_in[1];
    const float* hinit  = (const float*)d_in[2];
    const float* emb    = (const float*)d_in[3];
    const float* W1     = (const float*)d_in[4];
    const float* b1     = (const float*)d_in[5];
    const float* W2v    = (const float*)d_in[6];
    const float* b2     = (const float*)d_in[7];
    const float* Wiz    = (const float*)d_in[8];
    const float* biz    = (const float*)d_in[9];
    const float* Wir    = (const float*)d_in[10];
    const float* bir    = (const float*)d_in[11];
    const float* Wih    = (const float*)d_in[12];
    const float* bih    = (const float*)d_in[13];
    const float* Whz    = (const float*)d_in[14];
    const float* bhz    = (const float*)d_in[15];
    const float* Whr    = (const float*)d_in[16];
    const float* bhr    = (const float*)d_in[17];
    const float* Whh    = (const float*)d_in[18];
    const float* bhh    = (const float*)d_in[19];
    const float* Wout   = (const float*)d_in[20];
    const float* bout   = (const float*)d_in[21];

    float* out  = (float*)d_out;
    float* attn = out + (size_t)B_ * T_ * V_;   // outputs: (B,T,V) then (B,S,T)

    cudaFuncSetAttribute(scan_kernel,
                         cudaFuncAttributeMaxDynamicSharedMemorySize,
                         CSCAN_SMEM_BYTES);
    cudaFuncSetAttribute(out_gemm_kernel,
                         cudaFuncAttributeMaxDynamicSharedMemorySize,
                         GEMM_SMEM_BYTES);

    prep_kernel<<<512, 256>>>(inputs, ann, emb, W1, b1,
                              Wiz, biz, Wir, bir, Wih, bih);
    wout_cvt_kernel<<<8000, 256>>>(Wout);
    scan_kernel<<<64, 512, CSCAN_SMEM_BYTES>>>(ann, hinit, W1, W2v, b2,
                                               Wiz, Wir, Wih,
                                               Whz, bhz, Whr, bhr, Whh, bhh,
                                               attn);
    out_gemm_kernel<<<dim3(16, 500), 256, GEMM_SMEM_BYTES>>>(bout, out);
}

// round 14
// speedup vs baseline: 2.1397x; 1.2439x over previous
#include <cuda_runtime.h>
#include <cuda_bf16.h>
#include <cstdint>
#include <cstddef>

#define B_ 32
#define T_ 64
#define S_ 64
#define H_ 256
#define V_ 32000

// ---------------- device scratch (no runtime allocations allowed) ----------------
__device__ __align__(16) float g_annproj[B_ * S_ * H_];      // ann @ W1[H:] + b1
__device__ __align__(16) float g_xWi[B_ * T_ * 3 * H_];      // emb[tok] @ Wi*[H:] + bi*
__device__ __align__(16) float g_hidden[B_ * T_ * H_];       // scan outputs, tf32-rounded
__device__ __align__(16) float g_wout[(size_t)H_ * V_];      // Wout, tf32-rounded

__device__ __forceinline__ float f2tf_val(float x) {
    unsigned r;
    asm("cvt.rna.tf32.f32 %0, %1;" : "=r"(r) : "f"(x));
    return __uint_as_float(r);
}

// =========================================================================
// Kernel 1: precompute annproj and xWi.  16 output rows per block.
// grid.x = 512: kind = bid>>7 (0=ann,1=z,2=r,3=h), tile = bid&127.
// =========================================================================
__global__ __launch_bounds__(256) void prep_kernel(
    const int* __restrict__ inputs, const float* __restrict__ ann,
    const float* __restrict__ emb,
    const float* __restrict__ W1,  const float* __restrict__ b1,
    const float* __restrict__ Wiz, const float* __restrict__ biz,
    const float* __restrict__ Wir, const float* __restrict__ bir,
    const float* __restrict__ Wih, const float* __restrict__ bih)
{
    __shared__ float a_s[16][H_];
    __shared__ int s_tok[16];
    const int tid  = threadIdx.x;
    const int kind = blockIdx.x >> 7;
    const int r0   = (blockIdx.x & 127) * 16;

    if (kind != 0 && tid < 16) s_tok[tid] = inputs[r0 + tid];
    __syncthreads();

    #pragma unroll
    for (int it = 0; it < 4; it++) {
        int id = tid + it * 256;
        int r  = id >> 6;
        int q  = id & 63;
        const float* src = (kind == 0)
            ? ann + (size_t)(r0 + r) * H_
            : emb + (size_t)s_tok[r] * H_;
        ((float4*)&a_s[r][0])[q] = ((const float4*)src)[q];
    }
    __syncthreads();

    const float* W; const float* bias;
    if (kind == 0)      { W = W1  + H_ * H_; bias = b1;  }
    else if (kind == 1) { W = Wiz + H_ * H_; bias = biz; }
    else if (kind == 2) { W = Wir + H_ * H_; bias = bir; }
    else                { W = Wih + H_ * H_; bias = bih; }

    const int j = tid;
    float acc[16];
    const float bj = bias[j];
    #pragma unroll
    for (int r = 0; r < 16; r++) acc[r] = bj;

    const float* Wj = W + j;
    #pragma unroll 2
    for (int k4 = 0; k4 < H_ / 4; k4++) {
        float w0 = Wj[(size_t)(4 * k4 + 0) * H_];
        float w1 = Wj[(size_t)(4 * k4 + 1) * H_];
        float w2 = Wj[(size_t)(4 * k4 + 2) * H_];
        float w3 = Wj[(size_t)(4 * k4 + 3) * H_];
        #pragma unroll
        for (int r = 0; r < 16; r++) {
            float4 a4 = *(const float4*)&a_s[r][k4 * 4];
            acc[r] = fmaf(a4.x, w0, acc[r]);
            acc[r] = fmaf(a4.y, w1, acc[r]);
            acc[r] = fmaf(a4.z, w2, acc[r]);
            acc[r] = fmaf(a4.w, w3, acc[r]);
        }
    }

    if (kind == 0) {
        #pragma unroll
        for (int r = 0; r < 16; r++)
            g_annproj[(size_t)(r0 + r) * H_ + j] = acc[r];
    } else {
        const int g = kind - 1;
        #pragma unroll
        for (int r = 0; r < 16; r++)
            g_xWi[((size_t)(r0 + r) * 3 + g) * H_ + j] = acc[r];
    }
}

// =========================================================================
// Kernel 1b: round Wout to tf32 once.
// =========================================================================
__global__ __launch_bounds__(256) void wout_cvt_kernel(const float* __restrict__ Wout)
{
    size_t idx = ((size_t)blockIdx.x * 256 + threadIdx.x) * 4;
    float4 v = *(const float4*)(Wout + idx);
    v.x = f2tf_val(v.x); v.y = f2tf_val(v.y);
    v.z = f2tf_val(v.z); v.w = f2tf_val(v.w);
    *(float4*)(g_wout + idx) = v;
}

// =========================================================================
// Kernel 2: cluster-quad scan. Grid 128, cluster(4,1,1): cluster = one batch,
// rank r owns output columns [64r, 64r+64) of all 7 weight matrices.
// 512 threads/CTA, k-dim split 4 ways. Cross-CTA state via st.shared::cluster
// + barrier.cluster (3 per step).
// SMEM float offsets (per CTA):
// =========================================================================
#define Y_ANN  0        /* 4096: ann[b][s][own 64 j]     */
#define Y_AP   4096     /* 4096: annproj quarter          */
#define Y_H    8192     /* 256 : full h (peers fill rest) */
#define Y_Q    8448     /* 64  : q own columns            */
#define Y_HW   8512     /* 192 : hw[3][64]                */
#define Y_CI   8704     /* 192 : ci[3][64]                */
#define Y_CTX  8896     /* 256 : full ctx                 */
#define Y_W2   9152     /* 64  : W2 own columns           */
#define Y_U    9216     /* 256 : score partials, 4 ranks  */
#define Y_AW   9472     /* 64  */
#define Y_RED  9536     /* 8   */
#define Y_BIAS 9544     /* 192 : bh[3][64] own columns    */
#define Y_P1   9736     /* 768 : stage-1 kq>0 partials    */
#define Y_P5   10504    /* 576 : stage-5 kq>0 partials    */
#define Y_TOT  11080
#define QSCAN_SMEM_BYTES (Y_TOT * 4)

__device__ __forceinline__ void st_peer(uint32_t pbase, int foff, float v) {
    asm volatile("st.shared::cluster.f32 [%0], %1;"
                 :: "r"(pbase + 4u * (uint32_t)foff), "f"(v) : "memory");
}

__device__ __forceinline__ void cluster_sync_all() {
    __syncthreads();
    asm volatile("barrier.cluster.arrive.aligned;" ::: "memory");
    asm volatile("barrier.cluster.wait.aligned;" ::: "memory");
}

__global__ void __cluster_dims__(4, 1, 1) __launch_bounds__(512, 1) scan_kernel(
    const float* __restrict__ ann,  const float* __restrict__ hinit,
    const float* __restrict__ W1,   const float* __restrict__ W2v,
    const float* __restrict__ b2,
    const float* __restrict__ Wiz,  const float* __restrict__ Wir,
    const float* __restrict__ Wih,
    const float* __restrict__ Whz,  const float* __restrict__ bhz,
    const float* __restrict__ Whr,  const float* __restrict__ bhr,
    const float* __restrict__ Whh,  const float* __restrict__ bhh,
    float* __restrict__ attn_out)
{
    extern __shared__ float sm[];

    const int cid  = blockIdx.x;
    const int b    = cid >> 2;
    const int rank = cid & 3;
    const int j0   = rank * 64;
    const int tid  = threadIdx.x;

    uint32_t sbase = (uint32_t)__cvta_generic_to_shared(sm);
    uint32_t pb[3];
    {
        int pi = 0;
        #pragma unroll
        for (int r = 0; r < 4; r++) {
            if (r != rank) {
                uint32_t a;
                asm("mapa.shared::cluster.u32 %0, %1, %2;"
                    : "=r"(a) : "r"(sbase), "r"(r));
                pb[pi++] = a;
            }
        }
    }

    // ---- one-time init ----
    #pragma unroll
    for (int i = 0; i < 2; i++) {
        int idx = tid + i * 512;            // 0..1023 float4 slots
        int row = idx >> 4, q = idx & 15;   // 16 float4 per 64-float row
        ((float4*)(sm + Y_ANN))[idx] =
            *(const float4*)(ann + (size_t)b * S_ * H_ + (size_t)row * H_ + j0 + 4 * q);
        ((float4*)(sm + Y_AP))[idx] =
            *(const float4*)(g_annproj + (size_t)b * S_ * H_ + (size_t)row * H_ + j0 + 4 * q);
    }
    if (tid < 256) sm[Y_H + tid] = hinit[(size_t)b * H_ + tid];
    if (tid < 64)  sm[Y_W2 + tid] = W2v[j0 + tid];
    if (tid < 192) {
        int m = tid >> 6, jj = tid & 63;
        const float* bp = (m == 0 ? bhz : m == 1 ? bhr : bhh);
        sm[Y_BIAS + tid] = bp[j0 + jj];
    }
    const float b2v = b2[0];

    // ---- per-thread roles ----
    const int m1 = tid >> 7;            // 0..3 stage1 matrix; 0..2 valid stage5
    const int kq = (tid >> 5) & 3;      // k-quarter
    const int cp = tid & 31;            // column pair (2 cols of own 64)
    const float* Ws1 = (m1 == 0 ? W1 : m1 == 1 ? Whz : m1 == 2 ? Whr : Whh);
    const float* Ws5 = (m1 == 0 ? Wiz : m1 == 1 ? Wir : Wih);
    const float2* wb1 = (const float2*)(Ws1 + (size_t)(kq * 64) * H_ + j0 + 2 * cp);
    const float2* wb5 = (const float2*)(Ws5 + (size_t)(kq * 64) * H_ + j0 + 2 * cp);

    cluster_sync_all();

    for (int t = 0; t < T_; t++) {
        // ========== stage 1: q / hw own columns (k split by 4) ==========
        {
            float ax0 = 0.f, ay0 = 0.f, ax1 = 0.f, ay1 = 0.f;
            const float4* hp = (const float4*)(sm + Y_H) + kq * 16;
            #pragma unroll 4
            for (int k4 = 0; k4 < 16; k4++) {
                float4 h4 = hp[k4];
                float2 w0 = wb1[(4 * k4 + 0) * 128];
                float2 w1 = wb1[(4 * k4 + 1) * 128];
                float2 w2 = wb1[(4 * k4 + 2) * 128];
                float2 w3 = wb1[(4 * k4 + 3) * 128];
                ax0 = fmaf(h4.x, w0.x, ax0); ay0 = fmaf(h4.x, w0.y, ay0);
                ax1 = fmaf(h4.y, w1.x, ax1); ay1 = fmaf(h4.y, w1.y, ay1);
                ax0 = fmaf(h4.z, w2.x, ax0); ay0 = fmaf(h4.z, w2.y, ay0);
                ax1 = fmaf(h4.w, w3.x, ax1); ay1 = fmaf(h4.w, w3.y, ay1);
            }
            float sx = ax0 + ax1, sy = ay0 + ay1;
            if (kq != 0) {
                int base = Y_P1 + ((m1 * 32 + cp) * 3 + (kq - 1)) * 2;
                sm[base] = sx; sm[base + 1] = sy;
            }
            __syncthreads();
            if (kq == 0) {
                int base = Y_P1 + (m1 * 32 + cp) * 6;
                float ox = sx + sm[base]     + sm[base + 2] + sm[base + 4];
                float oy = sy + sm[base + 1] + sm[base + 3] + sm[base + 5];
                if (m1 == 0) {
                    sm[Y_Q + 2 * cp]     = ox;
                    sm[Y_Q + 2 * cp + 1] = oy;
                } else {
                    ox += sm[Y_BIAS + (m1 - 1) * 64 + 2 * cp];
                    oy += sm[Y_BIAS + (m1 - 1) * 64 + 2 * cp + 1];
                    sm[Y_HW + (m1 - 1) * 64 + 2 * cp]     = ox;
                    sm[Y_HW + (m1 - 1) * 64 + 2 * cp + 1] = oy;
                }
            }
        }
        __syncthreads();

        // ========== stage 2: partial scores over own 64 columns ==========
        {
            const int s = tid >> 3, p = tid & 7;
            float part = 0.f;
            #pragma unroll
            for (int i = 0; i < 8; i++) {
                int jj = p + 8 * ((i + s) & 7);    // conflict-free rotation
                float v = fmaxf(sm[Y_Q + jj] + sm[Y_AP + s * 64 + jj], 0.f);
                part = fmaf(v, sm[Y_W2 + jj], part);
            }
            part += __shfl_xor_sync(0xffffffffu, part, 1);
            part += __shfl_xor_sync(0xffffffffu, part, 2);
            part += __shfl_xor_sync(0xffffffffu, part, 4);
            if (p == 0) {
                sm[Y_U + rank * 64 + s] = part;
                st_peer(pb[0], Y_U + rank * 64 + s, part);
                st_peer(pb[1], Y_U + rank * 64 + s, part);
                st_peer(pb[2], Y_U + rank * 64 + s, part);
            }
        }
        cluster_sync_all();   // #1: score partials exchanged

        // ========== stage 3: softmax (computed on all ranks) ==========
        {
            float uv = -1e30f;
            if (tid < 64)
                uv = sm[Y_U + tid] + sm[Y_U + 64 + tid]
                   + sm[Y_U + 128 + tid] + sm[Y_U + 192 + tid] + b2v;
            if (tid < 64) {
                float m = uv;
                #pragma unroll
                for (int o = 16; o > 0; o >>= 1)
                    m = fmaxf(m, __shfl_xor_sync(0xffffffffu, m, o));
                if ((tid & 31) == 0) sm[Y_RED + (tid >> 5)] = m;
            }
            __syncthreads();
            float gmax = fmaxf(sm[Y_RED], sm[Y_RED + 1]);
            float ev = 0.f;
            if (tid < 64) {
                ev = __expf(uv - gmax);
                float ssum = ev;
                #pragma unroll
                for (int o = 16; o > 0; o >>= 1)
                    ssum += __shfl_xor_sync(0xffffffffu, ssum, o);
                if ((tid & 31) == 0) sm[Y_RED + 2 + (tid >> 5)] = ssum;
            }
            __syncthreads();
            if (tid < 64) {
                float aw = ev / (sm[Y_RED + 2] + sm[Y_RED + 3]);
                sm[Y_AW + tid] = aw;
                if (rank == 0)
                    attn_out[(size_t)b * S_ * T_ + (size_t)tid * T_ + t] = aw;
            }
        }
        __syncthreads();

        // ========== stage 4: context over own columns + xWi prefetch ======
        float xz = 0.f, xr = 0.f, xh = 0.f;
        if (tid < 64) {
            const size_t xo = ((size_t)(b * T_ + t) * 3) * H_ + j0 + tid;
            xz = g_xWi[xo]; xr = g_xWi[xo + H_]; xh = g_xWi[xo + 2 * H_];
            float ctx = 0.f;
            #pragma unroll
            for (int s2 = 0; s2 < 64; s2++)
                ctx = fmaf(sm[Y_AW + s2], sm[Y_ANN + s2 * 64 + tid], ctx);
            sm[Y_CTX + j0 + tid] = ctx;
            st_peer(pb[0], Y_CTX + j0 + tid, ctx);
            st_peer(pb[1], Y_CTX + j0 + tid, ctx);
            st_peer(pb[2], Y_CTX + j0 + tid, ctx);
        }
        cluster_sync_all();   // #2: full ctx assembled on all ranks

        // ========== stage 5: ci = ctx @ Wi*[:H] own columns ==========
        {
            float ax0 = 0.f, ay0 = 0.f, ax1 = 0.f, ay1 = 0.f;
            if (m1 < 3) {
                const float4* cpv = (const float4*)(sm + Y_CTX) + kq * 16;
                #pragma unroll 4
                for (int k4 = 0; k4 < 16; k4++) {
                    float4 c4 = cpv[k4];
                    float2 w0 = wb5[(4 * k4 + 0) * 128];
                    float2 w1 = wb5[(4 * k4 + 1) * 128];
                    float2 w2 = wb5[(4 * k4 + 2) * 128];
                    float2 w3 = wb5[(4 * k4 + 3) * 128];
                    ax0 = fmaf(c4.x, w0.x, ax0); ay0 = fmaf(c4.x, w0.y, ay0);
                    ax1 = fmaf(c4.y, w1.x, ax1); ay1 = fmaf(c4.y, w1.y, ay1);
                    ax0 = fmaf(c4.z, w2.x, ax0); ay0 = fmaf(c4.z, w2.y, ay0);
                    ax1 = fmaf(c4.w, w3.x, ax1); ay1 = fmaf(c4.w, w3.y, ay1);
                }
            }
            float sx = ax0 + ax1, sy = ay0 + ay1;
            if (m1 < 3 && kq != 0) {
                int base = Y_P5 + ((m1 * 32 + cp) * 3 + (kq - 1)) * 2;
                sm[base] = sx; sm[base + 1] = sy;
            }
            __syncthreads();
            if (m1 < 3 && kq == 0) {
                int base = Y_P5 + (m1 * 32 + cp) * 6;
                sm[Y_CI + m1 * 64 + 2 * cp] =
                    sx + sm[base] + sm[base + 2] + sm[base + 4];
                sm[Y_CI + m1 * 64 + 2 * cp + 1] =
                    sy + sm[base + 1] + sm[base + 3] + sm[base + 5];
            }
        }
        __syncthreads();

        // ========== stage 6: GRU gates for own 64 columns ==========
        if (tid < 64) {
            const int j = tid;
            float hprev = sm[Y_H + j0 + j];
            float z = 1.f / (1.f + __expf(-(sm[Y_CI + j]      + xz + sm[Y_HW + j])));
            float r = 1.f / (1.f + __expf(-(sm[Y_CI + 64 + j] + xr + sm[Y_HW + 64 + j])));
            float g = tanhf(sm[Y_CI + 128 + j] + xh + r * sm[Y_HW + 128 + j]);
            float hn = (1.f - z) * g + z * hprev;
            sm[Y_H + j0 + j] = hn;
            st_peer(pb[0], Y_H + j0 + j, hn);
            st_peer(pb[1], Y_H + j0 + j, hn);
            st_peer(pb[2], Y_H + j0 + j, hn);
            g_hidden[(size_t)(b * T_ + t) * H_ + j0 + j] = f2tf_val(hn);
        }
        cluster_sync_all();   // #3: full h_new on all ranks
    }
}

// =========================================================================
// Kernel 3: out[B*T, V] = hiddens @ Wout + bout (pre-rounded tf32 operands)
// tf32 mma m16n8k8, CTA tile 128x64, cp.async double-buffered.
// =========================================================================
#define GBM 128
#define GBN 64
#define GBK 32
#define AS_STRIDE 36
#define BS_STRIDE 72
#define GEMM_SMEM_FLOATS (2 * GBM * AS_STRIDE + 2 * GBK * BS_STRIDE)
#define GEMM_SMEM_BYTES  (GEMM_SMEM_FLOATS * 4)

__device__ __forceinline__ void cpasync16(void* smem_dst, const void* gsrc) {
    unsigned s = (unsigned)__cvta_generic_to_shared(smem_dst);
    asm volatile("cp.async.ca.shared.global [%0], [%1], 16;" :: "r"(s), "l"(gsrc));
}

__global__ __launch_bounds__(256) void out_gemm_kernel(
    const float* __restrict__ bout, float* __restrict__ out)
{
    extern __shared__ float gsm[];
    float* As = gsm;
    float* Bs = gsm + 2 * GBM * AS_STRIDE;

    const int tid  = threadIdx.x;
    const int wid  = tid >> 5;
    const int lane = tid & 31;
    const int g    = lane >> 2;
    const int tq   = lane & 3;
    const int wm   = wid & 3;
    const int wn   = wid >> 2;
    const int m0   = blockIdx.x * GBM;
    const int n0   = blockIdx.y * GBN;

    float c[2][4][4];
    #pragma unroll
    for (int a = 0; a < 2; a++)
        #pragma unroll
        for (int bb = 0; bb < 4; bb++)
            #pragma unroll
            for (int cc = 0; cc < 4; cc++) c[a][bb][cc] = 0.f;

    auto issue = [&](int kc_i) {
        const int kc = kc_i * GBK;
        float* Ab = As + (kc_i & 1) * GBM * AS_STRIDE;
        float* Bb = Bs + (kc_i & 1) * GBK * BS_STRIDE;
        #pragma unroll
        for (int it = 0; it < 4; it++) {
            int id = tid + it * 256;
            int m  = id >> 3;
            int q  = id & 7;
            cpasync16(&Ab[m * AS_STRIDE + q * 4],
                      &g_hidden[(size_t)(m0 + m) * H_ + kc + q * 4]);
        }
        #pragma unroll
        for (int it = 0; it < 2; it++) {
            int id = tid + it * 256;
            int k  = id >> 4;
            int nq = id & 15;
            cpasync16(&Bb[k * BS_STRIDE + nq * 4],
                      &g_wout[(size_t)(kc + k) * V_ + n0 + nq * 4]);
        }
        asm volatile("cp.async.commit_group;");
    };

    issue(0);

    for (int kc_i = 0; kc_i < H_ / GBK; kc_i++) {
        if (kc_i + 1 < H_ / GBK) {
            issue(kc_i + 1);
            asm volatile("cp.async.wait_group 1;");
        } else {
            asm volatile("cp.async.wait_group 0;");
        }
        __syncthreads();

        const float* Ab = As + (kc_i & 1) * GBM * AS_STRIDE;
        const float* Bb = Bs + (kc_i & 1) * GBK * BS_STRIDE;

        #pragma unroll
        for (int ks = 0; ks < 4; ks++) {
            const int K0 = ks * 8;
            unsigned af[2][4];
            #pragma unroll
            for (int mt = 0; mt < 2; mt++) {
                int row = wm * 32 + mt * 16 + g;
                af[mt][0] = __float_as_uint(Ab[(row    ) * AS_STRIDE + K0 + tq    ]);
                af[mt][1] = __float_as_uint(Ab[(row + 8) * AS_STRIDE + K0 + tq    ]);
                af[mt][2] = __float_as_uint(Ab[(row    ) * AS_STRIDE + K0 + tq + 4]);
                af[mt][3] = __float_as_uint(Ab[(row + 8) * AS_STRIDE + K0 + tq + 4]);
            }
            unsigned bf[4][2];
            #pragma unroll
            for (int nt = 0; nt < 4; nt++) {
                int col = wn * 32 + nt * 8 + g;
                bf[nt][0] = __float_as_uint(Bb[(K0 + tq    ) * BS_STRIDE + col]);
                bf[nt][1] = __float_as_uint(Bb[(K0 + tq + 4) * BS_STRIDE + col]);
            }
            #pragma unroll
            for (int mt = 0; mt < 2; mt++)
                #pragma unroll
                for (int nt = 0; nt < 4; nt++) {
                    asm volatile(
                        "mma.sync.aligned.m16n8k8.row.col.f32.tf32.tf32.f32 "
                        "{%0,%1,%2,%3}, {%4,%5,%6,%7}, {%8,%9}, {%0,%1,%2,%3};"
                        : "+f"(c[mt][nt][0]), "+f"(c[mt][nt][1]),
                          "+f"(c[mt][nt][2]), "+f"(c[mt][nt][3])
                        : "r"(af[mt][0]), "r"(af[mt][1]),
                          "r"(af[mt][2]), "r"(af[mt][3]),
                          "r"(bf[nt][0]), "r"(bf[nt][1]));
                }
        }
        __syncthreads();
    }

    #pragma unroll
    for (int mt = 0; mt < 2; mt++) {
        #pragma unroll
        for (int nt = 0; nt < 4; nt++) {
            int row = m0 + wm * 32 + mt * 16 + g;
            int col = n0 + wn * 32 + nt * 8 + 2 * tq;
            float bo0 = bout[col], bo1 = bout[col + 1];
            float2 v0 = make_float2(c[mt][nt][0] + bo0, c[mt][nt][1] + bo1);
            float2 v1 = make_float2(c[mt][nt][2] + bo0, c[mt][nt][3] + bo1);
            *(float2*)&out[(size_t)row * V_ + col]       = v0;
            *(float2*)&out[(size_t)(row + 8) * V_ + col] = v1;
        }
    }
}

// =========================================================================
extern "C" void kernel_launch(void* const* d_in, const int* in_sizes, int n_in,
                              void* d_out, int out_size)
{
    const int*   inputs = (const int*)  d_in[0];
    const float* ann    = (const float*)d_in[1];
    const float* hinit  = (const float*)d_in[2];
    const float* emb    = (const float*)d_in[3];
    const float* W1     = (const float*)d_in[4];
    const float* b1     = (const float*)d_in[5];
    const float* W2v    = (const float*)d_in[6];
    const float* b2     = (const float*)d_in[7];
    const float* Wiz    = (const float*)d_in[8];
    const float* biz    = (const float*)d_in[9];
    const float* Wir    = (const float*)d_in[10];
    const float* bir    = (const float*)d_in[11];
    const float* Wih    = (const float*)d_in[12];
    const float* bih    = (const float*)d_in[13];
    const float* Whz    = (const float*)d_in[14];
    const float* bhz    = (const float*)d_in[15];
    const float* Whr    = (const float*)d_in[16];
    const float* bhr    = (const float*)d_in[17];
    const float* Whh    = (const float*)d_in[18];
    const float* bhh    = (const float*)d_in[19];
    const float* Wout   = (const float*)d_in[20];
    const float* bout   = (const float*)d_in[21];

    float* out  = (float*)d_out;
    float* attn = out + (size_t)B_ * T_ * V_;   // outputs: (B,T,V) then (B,S,T)

    cudaFuncSetAttribute(scan_kernel,
                         cudaFuncAttributeMaxDynamicSharedMemorySize,
                         QSCAN_SMEM_BYTES);
    cudaFuncSetAttribute(out_gemm_kernel,
                         cudaFuncAttributeMaxDynamicSharedMemorySize,
                         GEMM_SMEM_BYTES);

    prep_kernel<<<512, 256>>>(inputs, ann, emb, W1, b1,
                              Wiz, biz, Wir, bir, Wih, bih);
    wout_cvt_kernel<<<8000, 256>>>(Wout);
    scan_kernel<<<128, 512, QSCAN_SMEM_BYTES>>>(ann, hinit, W1, W2v, b2,
                                                Wiz, Wir, Wih,
                                                Whz, bhz, Whr, bhr, Whh, bhh,
                                                attn);
    out_gemm_kernel<<<dim3(16, 500), 256, GEMM_SMEM_BYTES>>>(bout, out);
}